// round 5
// baseline (speedup 1.0000x reference)
#include <cuda_runtime.h>
#include <math.h>

// ---------------- problem constants ----------------
#define BB 4
#define NN 4096
#define DD 1024
#define HH 16
#define HD 64
#define MLP 4096
#define MM (BB*NN)          // 16384 rows

// ---------------- scratch (device globals; no allocation allowed) ------
__device__ float g_xn  [(size_t)MM * DD];
__device__ float g_q   [(size_t)MM * DD];
__device__ float g_k   [(size_t)MM * DD];
__device__ float g_v   [(size_t)MM * DD];
__device__ float g_attn[(size_t)MM * DD];
__device__ float g_x   [(size_t)MM * DD];
__device__ float g_h   [(size_t)MM * MLP];

// ---------------- LayerNorm (D=1024, biased var, eps=1e-5) -------------
__global__ __launch_bounds__(256) void ln_kernel(
    const float* __restrict__ X, const float* __restrict__ w,
    const float* __restrict__ b, float* __restrict__ Y)
{
    const int row = blockIdx.x;
    const int tid = threadIdx.x;
    const float* x = X + (size_t)row * DD;

    float4 xv = *(const float4*)(x + tid * 4);
    float s  = xv.x + xv.y + xv.z + xv.w;
    float s2 = fmaf(xv.x, xv.x, fmaf(xv.y, xv.y, fmaf(xv.z, xv.z, xv.w * xv.w)));

    #pragma unroll
    for (int o = 16; o; o >>= 1) {
        s  += __shfl_xor_sync(0xFFFFFFFFu, s,  o);
        s2 += __shfl_xor_sync(0xFFFFFFFFu, s2, o);
    }
    __shared__ float sh[8], sh2[8];
    const int lane = tid & 31, wid = tid >> 5;
    if (lane == 0) { sh[wid] = s; sh2[wid] = s2; }
    __syncthreads();
    float S = 0.f, S2 = 0.f;
    #pragma unroll
    for (int i = 0; i < 8; i++) { S += sh[i]; S2 += sh2[i]; }

    const float mean = S * (1.0f / DD);
    const float var  = S2 * (1.0f / DD) - mean * mean;
    const float inv  = rsqrtf(var + 1e-5f);

    float4 wv = *(const float4*)(w + tid * 4);
    float4 bv = *(const float4*)(b + tid * 4);
    float4 y;
    y.x = (xv.x - mean) * inv * wv.x + bv.x;
    y.y = (xv.y - mean) * inv * wv.y + bv.y;
    y.z = (xv.z - mean) * inv * wv.z + bv.z;
    y.w = (xv.w - mean) * inv * wv.w + bv.w;
    *(float4*)(Y + (size_t)row * DD + tid * 4) = y;
}

// ---------------- generic tiled GEMM: C = A[M,K] @ W[K,N] + bias (+epi) --
// EPI: 0 = bias only, 1 = bias + residual R, 2 = bias + exact GELU
#define BM 128
#define BN 128
#define BK 16

template<int EPI>
__global__ __launch_bounds__(256) void gemm_kernel(
    const float* __restrict__ A, const float* __restrict__ W,
    const float* __restrict__ bias, const float* __restrict__ R,
    float* __restrict__ C, int M, int N, int K)
{
    __shared__ float As[BK][BM];   // A tile, transposed (k-major)
    __shared__ float Ws[BK][BN];   // W tile

    const int tid = threadIdx.x;
    const int bm = blockIdx.y * BM;
    const int bn = blockIdx.x * BN;

    const int a_row = tid >> 2;          // 0..63 (x2 iterations)
    const int a_col = (tid & 3) * 4;     // 0,4,8,12
    const int w_row = tid >> 5;          // 0..7 (x2 iterations)
    const int w_col = (tid & 31) * 4;    // 0..124

    const int ty = tid >> 4;             // 0..15
    const int tx = tid & 15;             // 0..15

    float acc[8][8];
    #pragma unroll
    for (int i = 0; i < 8; i++)
        #pragma unroll
        for (int j = 0; j < 8; j++) acc[i][j] = 0.f;

    for (int k0 = 0; k0 < K; k0 += BK) {
        #pragma unroll
        for (int r = 0; r < 2; r++) {
            const int row = a_row + r * 64;
            float4 v = *(const float4*)(A + (size_t)(bm + row) * K + k0 + a_col);
            As[a_col + 0][row] = v.x;
            As[a_col + 1][row] = v.y;
            As[a_col + 2][row] = v.z;
            As[a_col + 3][row] = v.w;
        }
        #pragma unroll
        for (int r = 0; r < 2; r++) {
            const int row = w_row + r * 8;
            *(float4*)&Ws[row][w_col] =
                *(const float4*)(W + (size_t)(k0 + row) * N + bn + w_col);
        }
        __syncthreads();

        #pragma unroll
        for (int kk = 0; kk < BK; kk++) {
            float a[8], b[8];
            *(float4*)(a + 0) = *(const float4*)&As[kk][ty * 8 + 0];
            *(float4*)(a + 4) = *(const float4*)&As[kk][ty * 8 + 4];
            *(float4*)(b + 0) = *(const float4*)&Ws[kk][tx * 8 + 0];
            *(float4*)(b + 4) = *(const float4*)&Ws[kk][tx * 8 + 4];
            #pragma unroll
            for (int i = 0; i < 8; i++)
                #pragma unroll
                for (int j = 0; j < 8; j++)
                    acc[i][j] = fmaf(a[i], b[j], acc[i][j]);
        }
        __syncthreads();
    }

    // epilogue
    #pragma unroll
    for (int i = 0; i < 8; i++) {
        const int row = bm + ty * 8 + i;
        float* crow = C + (size_t)row * N + bn + tx * 8;
        const float* rrow = (EPI == 1) ? (R + (size_t)row * N + bn + tx * 8) : nullptr;
        float out[8];
        #pragma unroll
        for (int j = 0; j < 8; j++) {
            float vv = acc[i][j] + bias[bn + tx * 8 + j];
            if (EPI == 1) vv += rrow[j];
            if (EPI == 2) vv = 0.5f * vv * (1.0f + erff(vv * 0.70710678118654752f));
            out[j] = vv;
        }
        *(float4*)(crow + 0) = *(float4*)(out + 0);
        *(float4*)(crow + 4) = *(float4*)(out + 4);
    }
}

// ---------------- fused per-token linear attention ----------------
// The reference einsums reduce over the HEAD axis per position:
//   kv[d,e]  = sum_h fk[h,d] * v[h,e]        (64x64 per token)
//   qkv[h,e] = sum_d fq[h,d] * kv[d,e]
//   qk[h]    = sum_d fq[h,d] * ksum[d],  out = qkv/(qk+1e-6)
// One CTA per token; everything fits in SMEM.
__device__ __forceinline__ float elu1(float x) {
    return x > 0.f ? x + 1.0f : expf(x);   // elu(x)+1
}

__global__ __launch_bounds__(256) void attn_kernel(
    const float* __restrict__ Q, const float* __restrict__ K_,
    const float* __restrict__ V, float* __restrict__ O)
{
    __shared__ float fq[HH][HD];
    __shared__ float fk[HH][HD];
    __shared__ float vv[HH][HD];
    __shared__ float kv[HD][HD];
    __shared__ float ksum[HD];

    const size_t base = (size_t)blockIdx.x * DD;
    const int tid = threadIdx.x;

    // load + transform (1024 floats each; 256 threads x float4)
    {
        float4 q4 = *(const float4*)(Q  + base + tid * 4);
        float4 k4 = *(const float4*)(K_ + base + tid * 4);
        float4 v4 = *(const float4*)(V  + base + tid * 4);
        float* fqf = &fq[0][0];
        float* fkf = &fk[0][0];
        float* vvf = &vv[0][0];
        fqf[tid*4+0] = elu1(q4.x); fqf[tid*4+1] = elu1(q4.y);
        fqf[tid*4+2] = elu1(q4.z); fqf[tid*4+3] = elu1(q4.w);
        fkf[tid*4+0] = elu1(k4.x); fkf[tid*4+1] = elu1(k4.y);
        fkf[tid*4+2] = elu1(k4.z); fkf[tid*4+3] = elu1(k4.w);
        vvf[tid*4+0] = v4.x; vvf[tid*4+1] = v4.y;
        vvf[tid*4+2] = v4.z; vvf[tid*4+3] = v4.w;
    }
    __syncthreads();

    // ksum[d] = sum_h fk[h][d]
    if (tid < HD) {
        float s = 0.f;
        #pragma unroll
        for (int h = 0; h < HH; h++) s += fk[h][tid];
        ksum[tid] = s;
    }

    // kv[d][e] = sum_h fk[h][d] * v[h][e]
    {
        const int e = tid & 63;
        const int d0 = tid >> 6;       // 0..3
        #pragma unroll
        for (int j = 0; j < 16; j++) {
            const int d = d0 + j * 4;
            float s = 0.f;
            #pragma unroll
            for (int h = 0; h < HH; h++) s = fmaf(fk[h][d], vv[h][e], s);
            kv[d][e] = s;
        }
    }
    __syncthreads();

    // qkv / qk
    {
        const int e = tid & 63;
        const int h0 = tid >> 6;       // 0..3
        #pragma unroll
        for (int j = 0; j < 4; j++) {
            const int h = h0 + j * 4;
            float s = 0.f, sq = 0.f;
            #pragma unroll
            for (int d = 0; d < HD; d++) {
                const float f = fq[h][d];
                s  = fmaf(f, kv[d][e], s);
                sq = fmaf(f, ksum[d], sq);
            }
            O[base + h * HD + e] = s / (sq + 1e-6f);
        }
    }
}

// ---------------- launch ----------------
extern "C" void kernel_launch(void* const* d_in, const int* in_sizes, int n_in,
                              void* d_out, int out_size)
{
    const float* q_x    = (const float*)d_in[0];
    const float* ln1_w  = (const float*)d_in[1];
    const float* ln1_b  = (const float*)d_in[2];
    const float* wq     = (const float*)d_in[3];
    const float* bq     = (const float*)d_in[4];
    const float* wk     = (const float*)d_in[5];
    const float* bk     = (const float*)d_in[6];
    const float* wv     = (const float*)d_in[7];
    const float* bv     = (const float*)d_in[8];
    const float* wo     = (const float*)d_in[9];
    const float* bo     = (const float*)d_in[10];
    const float* ln2_w  = (const float*)d_in[11];
    const float* ln2_b  = (const float*)d_in[12];
    const float* fc_w   = (const float*)d_in[13];
    const float* fc_b   = (const float*)d_in[14];
    const float* proj_w = (const float*)d_in[15];
    const float* proj_b = (const float*)d_in[16];
    float* out = (float*)d_out;

    float *p_xn, *p_q, *p_k, *p_v, *p_attn, *p_x, *p_h;
    cudaGetSymbolAddress((void**)&p_xn,   g_xn);
    cudaGetSymbolAddress((void**)&p_q,    g_q);
    cudaGetSymbolAddress((void**)&p_k,    g_k);
    cudaGetSymbolAddress((void**)&p_v,    g_v);
    cudaGetSymbolAddress((void**)&p_attn, g_attn);
    cudaGetSymbolAddress((void**)&p_x,    g_x);
    cudaGetSymbolAddress((void**)&p_h,    g_h);

    const dim3 gD (DD  / BN, MM / BM);   // (8, 128)
    const dim3 gML(MLP / BN, MM / BM);   // (32, 128)

    // 1) xn = LN1(q_x)
    ln_kernel<<<MM, 256>>>(q_x, ln1_w, ln1_b, p_xn);
    // 2) q/k/v = xn @ w* + b*
    gemm_kernel<0><<<gD, 256>>>(p_xn, wq, bq, nullptr, p_q, MM, DD, DD);
    gemm_kernel<0><<<gD, 256>>>(p_xn, wk, bk, nullptr, p_k, MM, DD, DD);
    gemm_kernel<0><<<gD, 256>>>(p_xn, wv, bv, nullptr, p_v, MM, DD, DD);
    // 3) fused per-token linear attention
    attn_kernel<<<MM, 256>>>(p_q, p_k, p_v, p_attn);
    // 4) x = q_x + attn @ wo + bo
    gemm_kernel<1><<<gD, 256>>>(p_attn, wo, bo, q_x, p_x, MM, DD, DD);
    // 5) xn2 = LN2(x)
    ln_kernel<<<MM, 256>>>(p_x, ln2_w, ln2_b, p_xn);
    // 6) h = gelu(xn2 @ fc_w + fc_b)
    gemm_kernel<2><<<gML, 256>>>(p_xn, fc_w, fc_b, nullptr, p_h, MM, MLP, DD);
    // 7) out = x + h @ proj_w + proj_b
    gemm_kernel<1><<<gD, 256>>>(p_h, proj_w, proj_b, p_x, out, MM, DD, MLP);
}

// round 8
// speedup vs baseline: 2.2981x; 2.2981x over previous
#include <cuda_runtime.h>
#include <cuda_bf16.h>
#include <math.h>
#include <stdint.h>

// ---------------- problem constants ----------------
#define BB 4
#define NN 4096
#define DD 1024
#define HH 16
#define HD 64
#define MLP 4096
#define MM (BB*NN)          // 16384 rows
#define K3D (3*DD)          // 3072
#define K3M (3*MLP)         // 12288

// ---------------- scratch (device globals; no allocation allowed) ------
// packed bf16 activations: A' = [hi | lo | hi] along K
__device__ __align__(256) __nv_bfloat16 g_xnp[(size_t)MM * K3D];
__device__ __align__(256) __nv_bfloat16 g_ap [(size_t)MM * K3D];
__device__ __align__(256) __nv_bfloat16 g_hp [(size_t)MM * K3M];
__device__ __align__(256) float g_q[(size_t)MM * DD];
__device__ __align__(256) float g_k[(size_t)MM * DD];
__device__ __align__(256) float g_v[(size_t)MM * DD];
__device__ __align__(256) float g_x[(size_t)MM * DD];
// packed transposed weights: B' = [hi | hi | lo] along K,  [N][3K]
__device__ __align__(256) __nv_bfloat16 g_wqp[(size_t)DD * K3D];
__device__ __align__(256) __nv_bfloat16 g_wkp[(size_t)DD * K3D];
__device__ __align__(256) __nv_bfloat16 g_wvp[(size_t)DD * K3D];
__device__ __align__(256) __nv_bfloat16 g_wop[(size_t)DD * K3D];
__device__ __align__(256) __nv_bfloat16 g_fcp[(size_t)MLP * K3D];
__device__ __align__(256) __nv_bfloat16 g_pjp[(size_t)DD * K3M];

// ================= PTX helpers (compute_103-safe: sm_80+ features) =====
__device__ __forceinline__ uint32_t smem_u32(const void* p) {
    uint32_t a;
    asm("{ .reg .u64 t; cvta.to.shared.u64 t, %1; cvt.u32.u64 %0, t; }" : "=r"(a) : "l"(p));
    return a;
}
__device__ __forceinline__ void cp16(uint32_t sdst, const void* gsrc) {
    asm volatile("cp.async.cg.shared.global [%0], [%1], 16;" :: "r"(sdst), "l"(gsrc) : "memory");
}
__device__ __forceinline__ void ldm4(uint32_t* r, uint32_t a) {
    asm volatile("ldmatrix.sync.aligned.m8n8.x4.shared.b16 {%0,%1,%2,%3}, [%4];"
        : "=r"(r[0]), "=r"(r[1]), "=r"(r[2]), "=r"(r[3]) : "r"(a));
}
__device__ __forceinline__ void mma16816(float* d, const uint32_t* a, const uint32_t* b) {
    asm volatile("mma.sync.aligned.m16n8k16.row.col.f32.bf16.bf16.f32 "
        "{%0,%1,%2,%3},{%4,%5,%6,%7},{%8,%9},{%0,%1,%2,%3};"
        : "+f"(d[0]), "+f"(d[1]), "+f"(d[2]), "+f"(d[3])
        : "r"(a[0]), "r"(a[1]), "r"(a[2]), "r"(a[3]), "r"(b[0]), "r"(b[1]));
}

// ================= HMMA GEMM: C[M,N] = A[M,Keff] @ B[N,Keff]^T =========
// EPI: 0 = +bias (fp32), 1 = +bias+R (fp32), 2 = gelu(+bias) -> packed bf16
#define BM 128
#define BN 128
#define BKC 32
#define PITCH 40                       // bf16 per smem row (32 data + 8 pad)
#define TILE_SB (128 * PITCH * 2)      // 10240 B
#define STAGE_SB (2 * TILE_SB)         // A + B = 20480 B
#define NSTAGE 3
#define SMEM_BYTES (NSTAGE * STAGE_SB) // 61440 B

template<int EPI>
__global__ __launch_bounds__(256, 2) void mma_gemm(
    const __nv_bfloat16* __restrict__ A, const __nv_bfloat16* __restrict__ B,
    const float* __restrict__ bias, const float* __restrict__ Rres,
    float* __restrict__ Cf, __nv_bfloat16* __restrict__ Cp,
    int M, int N, int Keff)
{
    extern __shared__ char smem[];
    const uint32_t sb = smem_u32(smem);
    const int tid = threadIdx.x;
    const int bm = blockIdx.y * BM, bn = blockIdx.x * BN;
    const int w = tid >> 5, lane = tid & 31;
    const int wm = w & 1, wn = w >> 1;       // warp grid 2(m) x 4(n)

    float acc[4][4][4];
    #pragma unroll
    for (int i = 0; i < 4; i++)
        #pragma unroll
        for (int j = 0; j < 4; j++)
            #pragma unroll
            for (int t = 0; t < 4; t++) acc[i][j][t] = 0.f;

    const int KC = Keff / BKC;

    auto load_stage = [&](int st, int c) {
        const uint32_t s0 = sb + st * STAGE_SB;
        const int k0 = c * BKC;
        #pragma unroll
        for (int i = 0; i < 2; i++) {
            const int idx = tid + i * 256;      // 0..511
            const int r = idx >> 2, ch = idx & 3;
            cp16(s0 + r * 80 + ch * 16,
                 A + (size_t)(bm + r) * Keff + k0 + ch * 8);
            cp16(s0 + TILE_SB + r * 80 + ch * 16,
                 B + (size_t)(bn + r) * Keff + k0 + ch * 8);
        }
        asm volatile("cp.async.commit_group;" ::: "memory");
    };

    load_stage(0, 0);
    load_stage(1, 1);

    for (int c = 0; c < KC; c++) {
        const int st = c % NSTAGE;
        asm volatile("cp.async.wait_group 1;" ::: "memory");
        __syncthreads();

        // refill the stage freed last iteration (safe: all warps synced)
        if (c + 2 < KC) load_stage((c + 2) % NSTAGE, c + 2);
        else asm volatile("cp.async.commit_group;" ::: "memory");

        const uint32_t sA = sb + st * STAGE_SB;
        const uint32_t sB = sA + TILE_SB;

        #pragma unroll
        for (int ks = 0; ks < 2; ks++) {
            const int kc = ks * 16;
            uint32_t afr[4][4], bfr[4][2];
            #pragma unroll
            for (int mt = 0; mt < 4; mt++) {
                const int row = wm * 64 + mt * 16 + (lane & 15);
                const int col = kc + (lane >> 4) * 8;
                ldm4(afr[mt], sA + row * 80 + col * 2);
            }
            #pragma unroll
            for (int np = 0; np < 2; np++) {
                const int n = wn * 32 + np * 16 + ((lane >> 4) & 1) * 8 + (lane & 7);
                const int col = kc + ((lane >> 3) & 1) * 8;
                uint32_t r[4];
                ldm4(r, sB + n * 80 + col * 2);
                bfr[2 * np][0] = r[0]; bfr[2 * np][1] = r[1];
                bfr[2 * np + 1][0] = r[2]; bfr[2 * np + 1][1] = r[3];
            }
            #pragma unroll
            for (int mt = 0; mt < 4; mt++)
                #pragma unroll
                for (int nt = 0; nt < 4; nt++)
                    mma16816(acc[mt][nt], afr[mt], bfr[nt]);
        }
    }

    // -------- epilogue --------
    const int r0 = lane >> 2, cp2 = (lane & 3) * 2;
    #pragma unroll
    for (int mt = 0; mt < 4; mt++) {
        #pragma unroll
        for (int nt = 0; nt < 4; nt++) {
            const int col = bn + wn * 32 + nt * 8 + cp2;
            const float2 bv = *(const float2*)(bias + col);
            #pragma unroll
            for (int half = 0; half < 2; half++) {
                const int row = bm + wm * 64 + mt * 16 + r0 + half * 8;
                float v0 = acc[mt][nt][2 * half + 0] + bv.x;
                float v1 = acc[mt][nt][2 * half + 1] + bv.y;
                if (EPI == 1) {
                    const float2 rv = *(const float2*)(Rres + (size_t)row * N + col);
                    v0 += rv.x; v1 += rv.y;
                }
                if (EPI == 2) {
                    v0 = 0.5f * v0 * (1.0f + erff(v0 * 0.70710678118654752f));
                    v1 = 0.5f * v1 * (1.0f + erff(v1 * 0.70710678118654752f));
                    const __nv_bfloat16 h0 = __float2bfloat16(v0);
                    const __nv_bfloat16 h1 = __float2bfloat16(v1);
                    const __nv_bfloat16 l0 = __float2bfloat16(v0 - __bfloat162float(h0));
                    const __nv_bfloat16 l1 = __float2bfloat16(v1 - __bfloat162float(h1));
                    const size_t o = (size_t)row * (3 * (size_t)N) + col;
                    *(__nv_bfloat162*)(Cp + o)         = __nv_bfloat162(h0, h1);
                    *(__nv_bfloat162*)(Cp + o + N)     = __nv_bfloat162(l0, l1);
                    *(__nv_bfloat162*)(Cp + o + 2 * N) = __nv_bfloat162(h0, h1);
                } else {
                    *(float2*)(Cf + (size_t)row * N + col) = make_float2(v0, v1);
                }
            }
        }
    }
}

// ---------------- weight transpose + pack: W[K][N] -> T[N][3K] ---------
// T = [hi | hi | lo]
__global__ __launch_bounds__(256) void transpose_pack(
    const float* __restrict__ W, __nv_bfloat16* __restrict__ T, int K, int N)
{
    __shared__ float t[32][33];
    const int n0 = blockIdx.x * 32, k0 = blockIdx.y * 32;
    const int tx = threadIdx.x & 31, ty = threadIdx.x >> 5;  // 32 x 8
    #pragma unroll
    for (int i = 0; i < 32; i += 8)
        t[ty + i][tx] = W[(size_t)(k0 + ty + i) * N + n0 + tx];
    __syncthreads();
    #pragma unroll
    for (int i = 0; i < 32; i += 8) {
        const float v = t[tx][ty + i];
        const __nv_bfloat16 h = __float2bfloat16(v);
        const __nv_bfloat16 l = __float2bfloat16(v - __bfloat162float(h));
        const size_t o = (size_t)(n0 + ty + i) * (3 * (size_t)K) + k0 + tx;
        T[o]         = h;
        T[o + K]     = h;
        T[o + 2 * K] = l;
    }
}

// ---------------- LayerNorm -> packed bf16 [hi|lo|hi] ------------------
__global__ __launch_bounds__(256) void ln_pack_kernel(
    const float* __restrict__ X, const float* __restrict__ w,
    const float* __restrict__ b, __nv_bfloat16* __restrict__ Yp)
{
    const int row = blockIdx.x;
    const int tid = threadIdx.x;
    const float* x = X + (size_t)row * DD;

    float4 xv = *(const float4*)(x + tid * 4);
    float s  = xv.x + xv.y + xv.z + xv.w;
    float s2 = fmaf(xv.x, xv.x, fmaf(xv.y, xv.y, fmaf(xv.z, xv.z, xv.w * xv.w)));
    #pragma unroll
    for (int o = 16; o; o >>= 1) {
        s  += __shfl_xor_sync(0xFFFFFFFFu, s,  o);
        s2 += __shfl_xor_sync(0xFFFFFFFFu, s2, o);
    }
    __shared__ float sh[8], sh2[8];
    const int lane = tid & 31, wid = tid >> 5;
    if (lane == 0) { sh[wid] = s; sh2[wid] = s2; }
    __syncthreads();
    float S = 0.f, S2 = 0.f;
    #pragma unroll
    for (int i = 0; i < 8; i++) { S += sh[i]; S2 += sh2[i]; }
    const float mean = S * (1.0f / DD);
    const float var  = S2 * (1.0f / DD) - mean * mean;
    const float inv  = rsqrtf(var + 1e-5f);

    float4 wv = *(const float4*)(w + tid * 4);
    float4 bv = *(const float4*)(b + tid * 4);
    float y[4];
    y[0] = (xv.x - mean) * inv * wv.x + bv.x;
    y[1] = (xv.y - mean) * inv * wv.y + bv.y;
    y[2] = (xv.z - mean) * inv * wv.z + bv.z;
    y[3] = (xv.w - mean) * inv * wv.w + bv.w;

    __nv_bfloat16 h[4], l[4];
    #pragma unroll
    for (int t = 0; t < 4; t++) {
        h[t] = __float2bfloat16(y[t]);
        l[t] = __float2bfloat16(y[t] - __bfloat162float(h[t]));
    }
    const size_t o = (size_t)row * K3D + tid * 4;
    *(__nv_bfloat162*)(Yp + o)              = __nv_bfloat162(h[0], h[1]);
    *(__nv_bfloat162*)(Yp + o + 2)          = __nv_bfloat162(h[2], h[3]);
    *(__nv_bfloat162*)(Yp + o + DD)         = __nv_bfloat162(l[0], l[1]);
    *(__nv_bfloat162*)(Yp + o + DD + 2)     = __nv_bfloat162(l[2], l[3]);
    *(__nv_bfloat162*)(Yp + o + 2 * DD)     = __nv_bfloat162(h[0], h[1]);
    *(__nv_bfloat162*)(Yp + o + 2 * DD + 2) = __nv_bfloat162(h[2], h[3]);
}

// ---------------- fused per-token linear attention -> packed bf16 ------
__device__ __forceinline__ float elu1(float x) {
    return x > 0.f ? x + 1.0f : expf(x);
}

__global__ __launch_bounds__(256) void attn_kernel(
    const float* __restrict__ Q, const float* __restrict__ K_,
    const float* __restrict__ V, __nv_bfloat16* __restrict__ Op)
{
    __shared__ float fq[HH][HD];
    __shared__ float fk[HH][HD];
    __shared__ float vv[HH][HD];
    __shared__ float kv[HD][HD];
    __shared__ float ksum[HD];

    const size_t base  = (size_t)blockIdx.x * DD;
    const size_t base3 = (size_t)blockIdx.x * K3D;
    const int tid = threadIdx.x;

    {
        float4 q4 = *(const float4*)(Q  + base + tid * 4);
        float4 k4 = *(const float4*)(K_ + base + tid * 4);
        float4 v4 = *(const float4*)(V  + base + tid * 4);
        float* fqf = &fq[0][0]; float* fkf = &fk[0][0]; float* vvf = &vv[0][0];
        fqf[tid*4+0] = elu1(q4.x); fqf[tid*4+1] = elu1(q4.y);
        fqf[tid*4+2] = elu1(q4.z); fqf[tid*4+3] = elu1(q4.w);
        fkf[tid*4+0] = elu1(k4.x); fkf[tid*4+1] = elu1(k4.y);
        fkf[tid*4+2] = elu1(k4.z); fkf[tid*4+3] = elu1(k4.w);
        vvf[tid*4+0] = v4.x; vvf[tid*4+1] = v4.y;
        vvf[tid*4+2] = v4.z; vvf[tid*4+3] = v4.w;
    }
    __syncthreads();

    if (tid < HD) {
        float s = 0.f;
        #pragma unroll
        for (int h = 0; h < HH; h++) s += fk[h][tid];
        ksum[tid] = s;
    }
    {
        const int e = tid & 63;
        const int d0 = tid >> 6;
        #pragma unroll
        for (int j = 0; j < 16; j++) {
            const int d = d0 + j * 4;
            float s = 0.f;
            #pragma unroll
            for (int h = 0; h < HH; h++) s = fmaf(fk[h][d], vv[h][e], s);
            kv[d][e] = s;
        }
    }
    __syncthreads();
    {
        const int e = tid & 63;
        const int h0 = tid >> 6;
        #pragma unroll
        for (int j = 0; j < 4; j++) {
            const int h = h0 + j * 4;
            float s = 0.f, sq = 0.f;
            #pragma unroll
            for (int d = 0; d < HD; d++) {
                const float f = fq[h][d];
                s  = fmaf(f, kv[d][e], s);
                sq = fmaf(f, ksum[d], sq);
            }
            const float val = s / (sq + 1e-6f);
            const __nv_bfloat16 hi = __float2bfloat16(val);
            const __nv_bfloat16 lo = __float2bfloat16(val - __bfloat162float(hi));
            const size_t o = base3 + h * HD + e;
            Op[o]          = hi;
            Op[o + DD]     = lo;
            Op[o + 2 * DD] = hi;
        }
    }
}

// ---------------- launch ----------------
extern "C" void kernel_launch(void* const* d_in, const int* in_sizes, int n_in,
                              void* d_out, int out_size)
{
    const float* q_x    = (const float*)d_in[0];
    const float* ln1_w  = (const float*)d_in[1];
    const float* ln1_b  = (const float*)d_in[2];
    const float* wq     = (const float*)d_in[3];
    const float* bq     = (const float*)d_in[4];
    const float* wk     = (const float*)d_in[5];
    const float* bk     = (const float*)d_in[6];
    const float* wv     = (const float*)d_in[7];
    const float* bv     = (const float*)d_in[8];
    const float* wo     = (const float*)d_in[9];
    const float* bo     = (const float*)d_in[10];
    const float* ln2_w  = (const float*)d_in[11];
    const float* ln2_b  = (const float*)d_in[12];
    const float* fc_w   = (const float*)d_in[13];
    const float* fc_b   = (const float*)d_in[14];
    const float* proj_w = (const float*)d_in[15];
    const float* proj_b = (const float*)d_in[16];
    float* out = (float*)d_out;

    __nv_bfloat16 *xnp, *ap, *hp, *wqp, *wkp, *wvp, *wop, *fcp, *pjp;
    float *q, *k, *v, *x;
    cudaGetSymbolAddress((void**)&xnp, g_xnp);
    cudaGetSymbolAddress((void**)&ap,  g_ap);
    cudaGetSymbolAddress((void**)&hp,  g_hp);
    cudaGetSymbolAddress((void**)&q,   g_q);
    cudaGetSymbolAddress((void**)&k,   g_k);
    cudaGetSymbolAddress((void**)&v,   g_v);
    cudaGetSymbolAddress((void**)&x,   g_x);
    cudaGetSymbolAddress((void**)&wqp, g_wqp);
    cudaGetSymbolAddress((void**)&wkp, g_wkp);
    cudaGetSymbolAddress((void**)&wvp, g_wvp);
    cudaGetSymbolAddress((void**)&wop, g_wop);
    cudaGetSymbolAddress((void**)&fcp, g_fcp);
    cudaGetSymbolAddress((void**)&pjp, g_pjp);

    cudaFuncSetAttribute(mma_gemm<0>, cudaFuncAttributeMaxDynamicSharedMemorySize, SMEM_BYTES);
    cudaFuncSetAttribute(mma_gemm<1>, cudaFuncAttributeMaxDynamicSharedMemorySize, SMEM_BYTES);
    cudaFuncSetAttribute(mma_gemm<2>, cudaFuncAttributeMaxDynamicSharedMemorySize, SMEM_BYTES);

    // weight prep: transpose + bf16 hi/lo pack  [N][3K]
    transpose_pack<<<dim3(DD/32,  DD/32),  256>>>(wq,     wqp, DD,  DD);
    transpose_pack<<<dim3(DD/32,  DD/32),  256>>>(wk,     wkp, DD,  DD);
    transpose_pack<<<dim3(DD/32,  DD/32),  256>>>(wv,     wvp, DD,  DD);
    transpose_pack<<<dim3(DD/32,  DD/32),  256>>>(wo,     wop, DD,  DD);
    transpose_pack<<<dim3(MLP/32, DD/32),  256>>>(fc_w,   fcp, DD,  MLP);
    transpose_pack<<<dim3(DD/32,  MLP/32), 256>>>(proj_w, pjp, MLP, DD);

    const dim3 gD (DD  / BN, MM / BM);   // (8, 128)
    const dim3 gML(MLP / BN, MM / BM);   // (32, 128)

    // 1) xn = LN1(q_x) -> packed bf16
    ln_pack_kernel<<<MM, 256>>>(q_x, ln1_w, ln1_b, xnp);
    // 2) q/k/v = xn @ w* + b*  (fp32 out)
    mma_gemm<0><<<gD, 256, SMEM_BYTES>>>(xnp, wqp, bq, nullptr, q, nullptr, MM, DD, K3D);
    mma_gemm<0><<<gD, 256, SMEM_BYTES>>>(xnp, wkp, bk, nullptr, k, nullptr, MM, DD, K3D);
    mma_gemm<0><<<gD, 256, SMEM_BYTES>>>(xnp, wvp, bv, nullptr, v, nullptr, MM, DD, K3D);
    // 3) fused per-token linear attention -> packed bf16
    attn_kernel<<<MM, 256>>>(q, k, v, ap);
    // 4) x = q_x + attn @ wo + bo  (fp32 out)
    mma_gemm<1><<<gD, 256, SMEM_BYTES>>>(ap, wop, bo, q_x, x, nullptr, MM, DD, K3D);
    // 5) xn2 = LN2(x) -> packed bf16
    ln_pack_kernel<<<MM, 256>>>(x, ln2_w, ln2_b, xnp);
    // 6) h = gelu(xn2 @ fc_w + fc_b) -> packed bf16
    mma_gemm<2><<<gML, 256, SMEM_BYTES>>>(xnp, fcp, fc_b, nullptr, nullptr, hp, MM, MLP, K3D);
    // 7) out = x + h @ proj_w + proj_b  (fp32 out)
    mma_gemm<1><<<gD, 256, SMEM_BYTES>>>(hp, pjp, proj_b, x, out, nullptr, MM, DD, K3M);
}